// round 14
// baseline (speedup 1.0000x reference)
#include <cuda_runtime.h>
#include <cuda_fp16.h>
#include <math.h>
#include <stdint.h>

#define B_   8
#define S_   4096
#define E_   512
#define H_   8
#define D_   64
#define M_   (B_ * S_)      // 32768 rows
#define EPS_ 1e-6f

// -------- scratch (device globals; no allocations allowed) --------
__device__ __align__(16) float g_kvp[(size_t)B_ * H_ * 16 * D_ * D_];  // [bh][16][d][m]
__device__ __align__(16) float g_ksp[B_ * H_ * 4 * D_];                // [bh][4][d]
// KV^T per head, fp16 hi/lo, [bh][80][64]; row 64 = ksum, rows 65-79 zero.
__device__ __align__(16) __half g_kvth[64 * 80 * 64];
__device__ __align__(16) __half g_kvtl[64 * 80 * 64];
// fp16 operands
__device__ __align__(16) __half g_x16[(size_t)M_ * E_];
__device__ __align__(16) __half g_q16[(size_t)M_ * E_];
__device__ __align__(16) __half g_k16[(size_t)M_ * E_];
__device__ __align__(16) __half g_v16[(size_t)M_ * E_];
__device__ __align__(16) __half g_a16[(size_t)M_ * E_];
__device__ __align__(16) __half g_w16[4 * 512 * 512];   // transposed [n][k]

// ================= portable PTX helpers =================
static __device__ __forceinline__ uint32_t smem_u32(const void* p) {
    uint32_t a;
    asm("{ .reg .u64 t; cvta.to.shared.u64 t, %1; cvt.u32.u64 %0, t; }" : "=r"(a) : "l"(p));
    return a;
}
static __device__ __forceinline__ void ldsm4(uint32_t* r, uint32_t addr) {
    asm volatile("ldmatrix.sync.aligned.m8n8.x4.shared.b16 {%0,%1,%2,%3}, [%4];"
                 : "=r"(r[0]), "=r"(r[1]), "=r"(r[2]), "=r"(r[3]) : "r"(addr));
}
static __device__ __forceinline__ void ldsm4t(uint32_t* r, uint32_t addr) {
    asm volatile("ldmatrix.sync.aligned.m8n8.x4.trans.shared.b16 {%0,%1,%2,%3}, [%4];"
                 : "=r"(r[0]), "=r"(r[1]), "=r"(r[2]), "=r"(r[3]) : "r"(addr));
}
static __device__ __forceinline__ void mma16816(float* c, const uint32_t* a, const uint32_t* b) {
    asm volatile("mma.sync.aligned.m16n8k16.row.col.f32.f16.f16.f32 "
                 "{%0,%1,%2,%3}, {%4,%5,%6,%7}, {%8,%9}, {%0,%1,%2,%3};"
                 : "+f"(c[0]), "+f"(c[1]), "+f"(c[2]), "+f"(c[3])
                 : "r"(a[0]), "r"(a[1]), "r"(a[2]), "r"(a[3]), "r"(b[0]), "r"(b[1]));
}
static __device__ __forceinline__ void cp16(uint32_t dst, const void* src) {
    asm volatile("cp.async.cg.shared.global [%0], [%1], 16;" :: "r"(dst), "l"(src));
}
static __device__ __forceinline__ void cp_commit() {
    asm volatile("cp.async.commit_group;");
}
template <int N> static __device__ __forceinline__ void cp_wait() {
    asm volatile("cp.async.wait_group %0;" :: "n"(N));
}

// ============================================================
// A-resident fused GEMM. BM=128, BN=256, full K=512 of A in smem.
// A smem: 8 k-blocks x (128 rows x 128B, swizzled) = 128KB.
// B: 2-stage cp.async ring, stage = 256 n-rows x 128B = 32KB.
// 512 threads = 16 warps (4m x 4n), warp tile 32x64.
// ============================================================
#define APART  131072
#define BSTG   32768
#define FUSED_SMEM (APART + 2 * BSTG)   // 196608

// issue B stage: rows [n0, n0+256) cols [k0, k0+64) of Bsrc ([n][k] fp16)
static __device__ __forceinline__ void issue_b(
    uint32_t sb, int tid, const char* Bsrc, int n0, int k0)
{
#pragma unroll
    for (int i = 0; i < 4; i++) {
        int idx = i * 512 + tid;
        int r = idx >> 3, c = idx & 7;
        uint32_t so = (uint32_t)(r * 128 + ((c ^ (r & 7)) << 4));
        size_t go = ((size_t)(n0 + r) * 512 + k0) * 2 + c * 16;
        cp16(sb + so, Bsrc + go);
    }
    cp_commit();
}

// NPASS passes over (B-matrix, n-tile); bias/out per pass via arrays.
template <int NITER>
static __device__ __forceinline__ void fused_gemm_body(
    const __half* __restrict__ A, int m0,
    const char* const* bsrc,      // per-pass B base ([n][k])
    const float* const* biasp,    // per-pass bias
    __half* const* c16p,          // per-pass fp16 out (or null)
    float* const* c32p,           // per-pass fp32 out (or null)
    const bool* actp,
    const int* n0p)
{
    extern __shared__ __align__(1024) uint8_t dsm[];
    const int tid = threadIdx.x;
    const int wid = tid >> 5, lane = tid & 31;
    const int wm = wid & 3;
    const int wn = wid >> 2;
    const uint32_t sbase = smem_u32(dsm);

    // issue B stage 0 first (overlaps with A load)
    issue_b(sbase + APART, tid, bsrc[0], n0p[0], 0);

    // load A panel: 8 k-blocks x 1024 chunks = 8192 chunks / 512 thr
    const char* Ab = (const char*)A;
#pragma unroll
    for (int i = 0; i < 16; i++) {
        int idx = i * 512 + tid;
        int kb = idx >> 10, rem = idx & 1023;
        int r = rem >> 3, c = rem & 7;
        uint32_t so = (uint32_t)(kb * 16384 + r * 128 + ((c ^ (r & 7)) << 4));
        size_t go = ((size_t)(m0 + r) * 512 + kb * 64) * 2 + c * 16;
        *(uint4*)(dsm + so) = *(const uint4*)(Ab + go);
    }

    const int rA  = wm * 32 + (lane & 15);
    const int khA = (lane >> 4) & 1;
    const int swA = rA & 7;
    const int rBl = wn * 64 + (lane & 7) + ((lane >> 1) & 8);
    const int khB = (lane >> 3) & 1;
    const int g = lane >> 2, t4 = lane & 3;

    float acc[2][8][4];
#pragma unroll
    for (int i = 0; i < 2; i++)
#pragma unroll
        for (int j = 0; j < 8; j++)
#pragma unroll
            for (int t = 0; t < 4; t++) acc[i][j][t] = 0.f;

    for (int it = 0; it < NITER; it++) {
        const int kb = it & 7;
        if (it < NITER - 1) {
            int nx = it + 1;
            issue_b(sbase + APART + ((nx & 1) ? BSTG : 0), tid,
                    bsrc[nx >> 3], n0p[nx >> 3], (nx & 7) * 64);
            cp_wait<1>();
        } else {
            cp_wait<0>();
        }
        __syncthreads();

        const uint32_t sA = sbase + kb * 16384;
        const uint32_t sB = sbase + APART + ((it & 1) ? BSTG : 0);

#pragma unroll
        for (int ks = 0; ks < 4; ks++) {
            uint32_t a[8], bf[16];
            int cA = ks * 2 + khA;
            uint32_t aoff = (uint32_t)(rA * 128 + ((cA ^ swA) << 4));
            ldsm4(a + 0, sA + aoff);
            ldsm4(a + 4, sA + aoff + 2048);
#pragma unroll
            for (int p = 0; p < 4; p++) {
                int rB = rBl + p * 16;
                int cB = ks * 2 + khB;
                ldsm4(bf + 4 * p, sB + (uint32_t)(rB * 128 + ((cB ^ (rB & 7)) << 4)));
            }
#pragma unroll
            for (int mt = 0; mt < 2; mt++)
#pragma unroll
                for (int nt = 0; nt < 8; nt++)
                    mma16816(acc[mt][nt], a + 4 * mt, bf + nt * 2);
        }

        if (kb == 7) {
            // epilogue for this pass
            const int pass = it >> 3;
            const float* bias = biasp[pass];
            const bool act = actp[pass];
            __half* C16 = c16p[pass];
            float* C32 = c32p[pass];
            const int n0 = n0p[pass];
#pragma unroll
            for (int mt = 0; mt < 2; mt++) {
#pragma unroll
                for (int nt = 0; nt < 8; nt++) {
                    int row = m0 + wm * 32 + mt * 16 + g;
                    int col = n0 + wn * 64 + nt * 8 + t4 * 2;
                    float b0 = bias[col], b1 = bias[col + 1];
                    float f0 = acc[mt][nt][0] + b0;
                    float f1 = acc[mt][nt][1] + b1;
                    float f2 = acc[mt][nt][2] + b0;
                    float f3 = acc[mt][nt][3] + b1;
                    if (act) {
                        f0 = (f0 > 0.f) ? (f0 + 1.f) : __expf(f0);
                        f1 = (f1 > 0.f) ? (f1 + 1.f) : __expf(f1);
                        f2 = (f2 > 0.f) ? (f2 + 1.f) : __expf(f2);
                        f3 = (f3 > 0.f) ? (f3 + 1.f) : __expf(f3);
                    }
                    if (C16) {
                        *(__half2*)(C16 + (size_t)row * 512 + col)       = __floats2half2_rn(f0, f1);
                        *(__half2*)(C16 + (size_t)(row + 8) * 512 + col) = __floats2half2_rn(f2, f3);
                    } else {
                        *(float2*)(C32 + (size_t)row * 512 + col)       = make_float2(f0, f1);
                        *(float2*)(C32 + (size_t)(row + 8) * 512 + col) = make_float2(f2, f3);
                    }
                    acc[mt][nt][0] = 0.f; acc[mt][nt][1] = 0.f;
                    acc[mt][nt][2] = 0.f; acc[mt][nt][3] = 0.f;
                }
            }
        }
        __syncthreads();
    }
}

// qkv fused: grid (256), 512 threads. 6 passes (Q/K/V x 2 n-tiles), 48 iters.
__global__ __launch_bounds__(512, 1) void qkv_fused(const float* __restrict__ bq,
                                                    const float* __restrict__ bk,
                                                    const float* __restrict__ bv)
{
    const char* bsrc[6];
    const float* biasp[6];
    __half* c16p[6];
    float* c32p[6];
    bool actp[6];
    int n0p[6];
#pragma unroll
    for (int p = 0; p < 6; p++) {
        int mat = p >> 1;
        bsrc[p] = (const char*)(g_w16 + (size_t)mat * 262144);
        biasp[p] = (mat == 0) ? bq : (mat == 1) ? bk : bv;
        c16p[p] = (mat == 0) ? g_q16 : (mat == 1) ? g_k16 : g_v16;
        c32p[p] = nullptr;
        actp[p] = (mat < 2);
        n0p[p] = (p & 1) * 256;
    }
    fused_gemm_body<48>(g_x16, blockIdx.x * 128, bsrc, biasp, c16p, c32p, actp, n0p);
}

// out fused: grid (256), 512 threads. 2 passes, 16 iters. fp32 out.
__global__ __launch_bounds__(512, 1) void out_fused(float* __restrict__ out,
                                                    const float* __restrict__ bo)
{
    const char* bsrc[2];
    const float* biasp[2];
    __half* c16p[2];
    float* c32p[2];
    bool actp[2];
    int n0p[2];
#pragma unroll
    for (int p = 0; p < 2; p++) {
        bsrc[p] = (const char*)(g_w16 + (size_t)3 * 262144);
        biasp[p] = bo;
        c16p[p] = nullptr;
        c32p[p] = out;
        actp[p] = false;
        n0p[p] = p * 256;
    }
    fused_gemm_body<16>(g_a16, blockIdx.x * 128, bsrc, biasp, c16p, c32p, actp, n0p);
}

// ============================================================
// x -> fp16
__global__ __launch_bounds__(256) void split_x(const float* __restrict__ x)
{
    size_t i4 = ((size_t)blockIdx.x * 256 + threadIdx.x) * 4;
    float4 v = *(const float4*)(x + i4);
    *(__half2*)(g_x16 + i4)     = __floats2half2_rn(v.x, v.y);
    *(__half2*)(g_x16 + i4 + 2) = __floats2half2_rn(v.z, v.w);
}

// transpose weights: W [k][n] fp32 -> Wt [n][k] fp16. grid(16,16,4) block(32,8)
__global__ __launch_bounds__(256) void tsplit_w(const float* __restrict__ Wq,
                                                const float* __restrict__ Wk,
                                                const float* __restrict__ Wv,
                                                const float* __restrict__ Wo)
{
    const float* W = (blockIdx.z == 0) ? Wq : (blockIdx.z == 1) ? Wk
                   : (blockIdx.z == 2) ? Wv : Wo;
    __half* oh = g_w16 + (size_t)blockIdx.z * 262144;
    __shared__ float t[32][33];
    int nx = blockIdx.x * 32 + threadIdx.x;
    int k0 = blockIdx.y * 32;
#pragma unroll
    for (int j = 0; j < 4; j++)
        t[threadIdx.y + j * 8][threadIdx.x] = W[(size_t)(k0 + threadIdx.y + j * 8) * 512 + nx];
    __syncthreads();
#pragma unroll
    for (int j = 0; j < 4; j++) {
        int nr = blockIdx.x * 32 + threadIdx.y + j * 8;
        int kc = k0 + threadIdx.x;
        oh[(size_t)nr * 512 + kc] = __float2half(t[threadIdx.x][threadIdx.y + j * 8]);
    }
}

// ============================================================
// KV state via tensor cores (R9 proven): partial kv[d][m] = sum_s k[s,d]*v[s,m].
__global__ __launch_bounds__(256) void kv_mma()
{
    const int bh = blockIdx.y;
    const int b = bh >> 3, h = bh & 7;
    const int tid = threadIdx.x;
    const int wid = tid >> 5, lane = tid & 31;
    const int sub = wid >> 1, nh = wid & 1;

    __shared__ __align__(1024) __half sK[128 * 64];
    __shared__ __align__(1024) __half sV[128 * 64];
    const uint32_t kb = smem_u32(sK), vb = smem_u32(sV);

    float acc[4][4][4];
#pragma unroll
    for (int i = 0; i < 4; i++)
#pragma unroll
        for (int j = 0; j < 4; j++)
#pragma unroll
            for (int t = 0; t < 4; t++) acc[i][j][t] = 0.f;

    const char* gk = (const char*)g_k16 + ((size_t)(b * S_ + blockIdx.x * 1024)) * 1024 + h * 128;
    const char* gv = (const char*)g_v16 + ((size_t)(b * S_ + blockIdx.x * 1024)) * 1024 + h * 128;

    const int rAl = ((lane >> 4) & 1) * 8 + (lane & 7);
    const int cA16 = (lane >> 3) & 1;
    const int rBl = ((lane >> 3) & 1) * 8 + (lane & 7);
    const int cB16 = (lane >> 4) & 1;

    for (int t = 0; t < 8; t++) {
#pragma unroll
        for (int i = 0; i < 4; i++) {
            int idx = i * 256 + tid;
            int r = idx >> 3, c = idx & 7;
            uint32_t so = (uint32_t)(r * 128 + ((c ^ (r & 7)) << 4));
            size_t go = (size_t)(t * 128 + r) * 1024 + c * 16;
            *(uint4*)((char*)sK + so) = *(const uint4*)(gk + go);
            *(uint4*)((char*)sV + so) = *(const uint4*)(gv + go);
        }
        __syncthreads();

#pragma unroll
        for (int kst = 0; kst < 2; kst++) {
            int s0 = sub * 32 + kst * 16;
            uint32_t a[4][4], bf[2][4];
#pragma unroll
            for (int mt = 0; mt < 4; mt++) {
                int r = s0 + rAl;
                int c = mt * 2 + cA16;
                ldsm4t(a[mt], kb + (uint32_t)(r * 128 + ((c ^ (r & 7)) << 4)));
            }
#pragma unroll
            for (int p = 0; p < 2; p++) {
                int r = s0 + rBl;
                int c = nh * 4 + p * 2 + cB16;
                ldsm4t(bf[p], vb + (uint32_t)(r * 128 + ((c ^ (r & 7)) << 4)));
            }
#pragma unroll
            for (int mt = 0; mt < 4; mt++)
#pragma unroll
                for (int nt = 0; nt < 4; nt++)
                    mma16816(acc[mt][nt], a[mt], &bf[nt >> 1][(nt & 1) * 2]);
        }
        __syncthreads();
    }

    float* ob = g_kvp + ((size_t)bh * 16 + blockIdx.x * 4 + sub) * 4096 + nh * 32;
    const int g = lane >> 2, t4 = lane & 3;
#pragma unroll
    for (int mt = 0; mt < 4; mt++) {
#pragma unroll
        for (int nt = 0; nt < 4; nt++) {
            int d = mt * 16 + g, col = nt * 8 + t4 * 2;
            *(float2*)(ob + (size_t)d * 64 + col)       = make_float2(acc[mt][nt][0], acc[mt][nt][1]);
            *(float2*)(ob + (size_t)(d + 8) * 64 + col) = make_float2(acc[mt][nt][2], acc[mt][nt][3]);
        }
    }
}

// ksum partials from fp16 k: grid (64, 4), block 256
__global__ __launch_bounds__(256) void ksum_part()
{
    const int bh = blockIdx.x;
    const int grp = blockIdx.y;
    const int b = bh >> 3, h = bh & 7;
    const int tid = threadIdx.x;
    const int d = tid & 63, sg = tid >> 6;

    float s = 0.f;
    const __half* kp = g_k16 + ((size_t)b * S_) * 512 + h * 64 + d;
#pragma unroll 4
    for (int s0 = grp * 1024 + sg; s0 < (grp + 1) * 1024; s0 += 4)
        s += __half2float(kp[(size_t)s0 * 512]);

    __shared__ float red[256];
    red[tid] = s;
    __syncthreads();
    if (sg == 0)
        g_ksp[(bh * 4 + grp) * 64 + d] = red[d] + red[64 + d] + red[128 + d] + red[192 + d];
}

// reduce partials -> KV^T fp16 hi/lo [bh][80][64]. grid 64, block 256.
__global__ __launch_bounds__(256) void kv_reduce()
{
    const int bh = blockIdx.x;
    const int tid = threadIdx.x;
    for (int idx = tid; idx < 4096; idx += 256) {
        float s = 0.f;
#pragma unroll
        for (int c = 0; c < 16; c++)
            s += g_kvp[((size_t)bh * 16 + c) * 4096 + idx];
        int d = idx >> 6, m = idx & 63;
        __half hi = __float2half(s);
        size_t o = ((size_t)bh * 80 + m) * 64 + d;
        g_kvth[o] = hi;
        g_kvtl[o] = __float2half(s - __half2float(hi));
    }
    if (tid < 64) {
        float s = g_ksp[(bh * 4 + 0) * 64 + tid] + g_ksp[(bh * 4 + 1) * 64 + tid]
                + g_ksp[(bh * 4 + 2) * 64 + tid] + g_ksp[(bh * 4 + 3) * 64 + tid];
        __half hi = __float2half(s);
        size_t o = ((size_t)bh * 80 + 64) * 64 + tid;
        g_kvth[o] = hi;
        g_kvtl[o] = __float2half(s - __half2float(hi));
    }
    for (int idx = tid; idx < 15 * 64; idx += 256) {
        size_t o = ((size_t)bh * 80 + 65) * 64 + idx;
        g_kvth[o] = __float2half(0.f);
        g_kvtl[o] = __float2half(0.f);
    }
}

// ============================================================
// Attention readout via HMMA (R10 proven): per (bh, 128-row tile),
// C[128, 80] = q_tile @ (KVT_hi + KVT_lo)^T ; col 64 = denominator.
// grid (32, 64), block 256 = 8 warps x 16 rows.
__global__ __launch_bounds__(256) void attn_mma()
{
    const int bh = blockIdx.y;
    const int b = bh >> 3, h = bh & 7;
    const int l0 = blockIdx.x * 128;
    const int tid = threadIdx.x;
    const int wid = tid >> 5, lane = tid & 31;

    __shared__ __align__(1024) __half sQ[128 * 64];
    __shared__ __align__(1024) __half sB[2][80 * 64];
    __shared__ float sDen[128];

#pragma unroll
    for (int i = 0; i < 4; i++) {
        int idx = i * 256 + tid;
        int r = idx >> 3, c = idx & 7;
        uint32_t so = (uint32_t)(r * 128 + ((c ^ (r & 7)) << 4));
        size_t go = (((size_t)(b * S_ + l0 + r)) * 512 + h * 64) * 2 + c * 16;
        *(uint4*)((char*)sQ + so) = *(const uint4*)((const char*)g_q16 + go);
    }
#pragma unroll
    for (int i = 0; i < 5; i++) {
        int idx = i * 256 + tid;
        int r = idx >> 3, c = idx & 7;   // r in 0..159
        int arr = r >= 80;
        int rr = arr ? r - 80 : r;
        uint32_t so = (uint32_t)(rr * 128 + ((c ^ (rr & 7)) << 4));
        size_t go = (((size_t)bh * 80 + rr) * 64) * 2 + c * 16;
        const char* src = arr ? (const char*)g_kvtl : (const char*)g_kvth;
        *(uint4*)((char*)sB[arr] + so) = *(const uint4*)(src + go);
    }
    __syncthreads();

    const uint32_t qb = smem_u32(sQ);
    const uint32_t bb0 = smem_u32(sB[0]);
    const uint32_t bb1 = smem_u32(sB[1]);

    const int rA  = wid * 16 + (lane & 15);
    const int khA = (lane >> 4) & 1;
    const int swA = rA & 7;
    const int rBl = (lane & 7) + ((lane >> 1) & 8);
    const int khB = (lane >> 3) & 1;

    float acc[10][4];
#pragma unroll
    for (int n = 0; n < 10; n++)
#pragma unroll
        for (int t = 0; t < 4; t++) acc[n][t] = 0.f;

#pragma unroll
    for (int ks = 0; ks < 4; ks++) {
        uint32_t a[4];
        int cA = ks * 2 + khA;
        ldsm4(a, qb + (uint32_t)(rA * 128 + ((cA ^ swA) << 4)));
#pragma unroll
        for (int arr = 0; arr < 2; arr++) {
            uint32_t base = arr ? bb1 : bb0;
#pragma unroll
            for (int p = 0; p < 5; p++) {
                uint32_t bf[4];
                int rB = p * 16 + rBl;
                int cB = ks * 2 + khB;
                ldsm4(bf, base + (uint32_t)(rB * 128 + ((cB ^ (rB & 7)) << 4)));
                mma16816(acc[p * 2], a, bf + 0);
                if (p < 4) mma16816(acc[p * 2 + 1], a, bf + 2);
            }
        }
    }

    const int g = lane >> 2, t4 = lane & 3;
    if (t4 == 0) {
        sDen[wid * 16 + g]     = acc[8][0];
        sDen[wid * 16 + g + 8] = acc[8][2];
    }
    __syncthreads();

    int row0 = wid * 16 + g;
    float z0 = 1.0f / (sDen[row0] + EPS_);
    float z1 = 1.0f / (sDen[row0 + 8] + EPS_);
    __half* o0 = g_a16 + ((size_t)(b * S_ + l0 + row0)) * 512 + h * 64;
    __half* o1 = o0 + (size_t)8 * 512;
#pragma unroll
    for (int nt = 0; nt < 8; nt++) {
        int col = nt * 8 + t4 * 2;
        *(__half2*)(o0 + col) = __floats2half2_rn(acc[nt][0] * z0, acc[nt][1] * z0);
        *(__half2*)(o1 + col) = __floats2half2_rn(acc[nt][2] * z1, acc[nt][3] * z1);
    }
}

// ============================================================
extern "C" void kernel_launch(void* const* d_in, const int* in_sizes, int n_in,
                              void* d_out, int out_size)
{
    const float* x  = (const float*)d_in[0];
    const float* Wq = (const float*)d_in[1];
    const float* bq = (const float*)d_in[2];
    const float* Wk = (const float*)d_in[3];
    const float* bk = (const float*)d_in[4];
    const float* Wv = (const float*)d_in[5];
    const float* bv = (const float*)d_in[6];
    const float* Wo = (const float*)d_in[7];
    const float* bo = (const float*)d_in[8];
    float* out = (float*)d_out;

    cudaFuncSetAttribute(qkv_fused, cudaFuncAttributeMaxDynamicSharedMemorySize, FUSED_SMEM);
    cudaFuncSetAttribute(out_fused, cudaFuncAttributeMaxDynamicSharedMemorySize, FUSED_SMEM);

    split_x<<<(M_ * E_) / (256 * 4), 256>>>(x);
    tsplit_w<<<dim3(16, 16, 4), dim3(32, 8)>>>(Wq, Wk, Wv, Wo);
    qkv_fused<<<M_ / 128, 512, FUSED_SMEM>>>(bq, bk, bv);
    kv_mma<<<dim3(4, 64), 256>>>();
    ksum_part<<<dim3(64, 4), 256>>>();
    kv_reduce<<<64, 256>>>();
    attn_mma<<<dim3(32, 64), 256>>>();
    out_fused<<<M_ / 128, 512, FUSED_SMEM>>>(out, bo);
}

// round 15
// speedup vs baseline: 1.7575x; 1.7575x over previous
#include <cuda_runtime.h>
#include <cuda_fp16.h>
#include <math.h>
#include <stdint.h>

#define B_   8
#define S_   4096
#define E_   512
#define H_   8
#define D_   64
#define M_   (B_ * S_)      // 32768 rows
#define EPS_ 1e-6f

// -------- scratch (device globals; no allocations allowed) --------
__device__ __align__(16) float g_kvp[(size_t)B_ * H_ * 16 * D_ * D_];  // [bh][16][d][m]
__device__ __align__(16) float g_ksp[B_ * H_ * 4 * D_];                // [bh][4][d]
// KV^T per head, fp16 hi/lo, [bh][80][64]; row 64 = ksum, rows 65-79 zero.
__device__ __align__(16) __half g_kvth[64 * 80 * 64];
__device__ __align__(16) __half g_kvtl[64 * 80 * 64];
// fp16 operands
__device__ __align__(16) __half g_x16[(size_t)M_ * E_];
__device__ __align__(16) __half g_q16[(size_t)M_ * E_];
__device__ __align__(16) __half g_k16[(size_t)M_ * E_];
__device__ __align__(16) __half g_v16[(size_t)M_ * E_];
__device__ __align__(16) __half g_a16[(size_t)M_ * E_];
__device__ __align__(16) __half g_w16[4 * 512 * 512];   // transposed [n][k]

// ================= portable PTX helpers =================
static __device__ __forceinline__ uint32_t smem_u32(const void* p) {
    uint32_t a;
    asm("{ .reg .u64 t; cvta.to.shared.u64 t, %1; cvt.u32.u64 %0, t; }" : "=r"(a) : "l"(p));
    return a;
}
static __device__ __forceinline__ void ldsm4(uint32_t* r, uint32_t addr) {
    asm volatile("ldmatrix.sync.aligned.m8n8.x4.shared.b16 {%0,%1,%2,%3}, [%4];"
                 : "=r"(r[0]), "=r"(r[1]), "=r"(r[2]), "=r"(r[3]) : "r"(addr));
}
static __device__ __forceinline__ void ldsm4t(uint32_t* r, uint32_t addr) {
    asm volatile("ldmatrix.sync.aligned.m8n8.x4.trans.shared.b16 {%0,%1,%2,%3}, [%4];"
                 : "=r"(r[0]), "=r"(r[1]), "=r"(r[2]), "=r"(r[3]) : "r"(addr));
}
static __device__ __forceinline__ void mma16816(float* c, const uint32_t* a, const uint32_t* b) {
    asm volatile("mma.sync.aligned.m16n8k16.row.col.f32.f16.f16.f32 "
                 "{%0,%1,%2,%3}, {%4,%5,%6,%7}, {%8,%9}, {%0,%1,%2,%3};"
                 : "+f"(c[0]), "+f"(c[1]), "+f"(c[2]), "+f"(c[3])
                 : "r"(a[0]), "r"(a[1]), "r"(a[2]), "r"(a[3]), "r"(b[0]), "r"(b[1]));
}
static __device__ __forceinline__ void cp16(uint32_t dst, const void* src) {
    asm volatile("cp.async.cg.shared.global [%0], [%1], 16;" :: "r"(dst), "l"(src));
}
static __device__ __forceinline__ void cp_commit() {
    asm volatile("cp.async.commit_group;");
}
template <int N> static __device__ __forceinline__ void cp_wait() {
    asm volatile("cp.async.wait_group %0;" :: "n"(N));
}

// ============================================================
// HMMA fp16 GEMM (R13 proven), BM=128 BN=256 BK=64, 512 threads (16 warps,
// 4m x 4n), warp tile 32x64, 2-stage cp.async pipeline.
// Dynamic SMEM 96KB: 2 stages x (A 16K | B 32K), XOR-swizzled 16B chunks.
// ============================================================
#define GSTAGE 49152
#define GEMM_DSMEM (2 * GSTAGE)

static __device__ __forceinline__ void gemm_issue(
    uint32_t sb, int tid, int k0, int m0, int n0,
    const char* Ab, const char* Bb)
{
#pragma unroll
    for (int i = 0; i < 2; i++) {
        int idx = i * 512 + tid;
        int r = idx >> 3, c = idx & 7;
        uint32_t so = (uint32_t)(r * 128 + ((c ^ (r & 7)) << 4));
        size_t go = ((size_t)(m0 + r) * 512 + k0) * 2 + c * 16;
        cp16(sb + so, Ab + go);
    }
#pragma unroll
    for (int i = 0; i < 4; i++) {
        int idx = i * 512 + tid;
        int r = idx >> 3, c = idx & 7;
        uint32_t so = (uint32_t)(16384 + r * 128 + ((c ^ (r & 7)) << 4));
        size_t go = ((size_t)(n0 + r) * 512 + k0) * 2 + c * 16;
        cp16(sb + so, Bb + go);
    }
    cp_commit();
}

static __device__ __forceinline__ void gemm_mma_body(
    const __half* __restrict__ A, const __half* __restrict__ Bm,
    const float* __restrict__ bias, float* __restrict__ C32,
    __half* __restrict__ C16, bool act, int m0, int n0)
{
    extern __shared__ __align__(1024) uint8_t dsm[];
    const int tid = threadIdx.x;
    const int wid = tid >> 5, lane = tid & 31;
    const int wm = wid & 3;          // 0..3 -> 32-row m group
    const int wn = wid >> 2;         // 0..3 -> 64-col n group
    const uint32_t sbase = smem_u32(dsm);

    float acc[2][8][4];
#pragma unroll
    for (int i = 0; i < 2; i++)
#pragma unroll
        for (int j = 0; j < 8; j++)
#pragma unroll
            for (int t = 0; t < 4; t++) acc[i][j][t] = 0.f;

    const int rA  = wm * 32 + (lane & 15);
    const int khA = (lane >> 4) & 1;
    const int swA = rA & 7;
    const int rBl = wn * 64 + (lane & 7) + ((lane >> 1) & 8);
    const int khB = (lane >> 3) & 1;

    const char* Ab = (const char*)A;
    const char* Bb = (const char*)Bm;

    gemm_issue(sbase, tid, 0, m0, n0, Ab, Bb);

    for (int kb = 0; kb < 8; kb++) {
        if (kb < 7) {
            gemm_issue(sbase + ((kb + 1) & 1) * GSTAGE, tid, (kb + 1) * 64, m0, n0, Ab, Bb);
            cp_wait<1>();
        } else {
            cp_wait<0>();
        }
        __syncthreads();

        const uint32_t st = sbase + (kb & 1) * GSTAGE;
        const uint32_t sA = st, sB = st + 16384;

#pragma unroll
        for (int ks = 0; ks < 4; ks++) {
            uint32_t a[8], bf[16];
            int cA = ks * 2 + khA;
            uint32_t aoff = (uint32_t)(rA * 128 + ((cA ^ swA) << 4));
            ldsm4(a + 0, sA + aoff);
            ldsm4(a + 4, sA + aoff + 2048);
#pragma unroll
            for (int p = 0; p < 4; p++) {
                int rB = rBl + p * 16;
                int cB = ks * 2 + khB;
                ldsm4(bf + 4 * p, sB + (uint32_t)(rB * 128 + ((cB ^ (rB & 7)) << 4)));
            }
#pragma unroll
            for (int mt = 0; mt < 2; mt++)
#pragma unroll
                for (int nt = 0; nt < 8; nt++)
                    mma16816(acc[mt][nt], a + 4 * mt, bf + nt * 2);
        }
        __syncthreads();
    }

    const int g = lane >> 2, t4 = lane & 3;
#pragma unroll
    for (int mt = 0; mt < 2; mt++) {
#pragma unroll
        for (int nt = 0; nt < 8; nt++) {
            int row = m0 + wm * 32 + mt * 16 + g;
            int col = n0 + wn * 64 + nt * 8 + t4 * 2;
            float b0 = bias[col], b1 = bias[col + 1];
            float f0 = acc[mt][nt][0] + b0;
            float f1 = acc[mt][nt][1] + b1;
            float f2 = acc[mt][nt][2] + b0;
            float f3 = acc[mt][nt][3] + b1;
            if (act) {
                f0 = (f0 > 0.f) ? (f0 + 1.f) : __expf(f0);
                f1 = (f1 > 0.f) ? (f1 + 1.f) : __expf(f1);
                f2 = (f2 > 0.f) ? (f2 + 1.f) : __expf(f2);
                f3 = (f3 > 0.f) ? (f3 + 1.f) : __expf(f3);
            }
            if (C16) {
                *(__half2*)(C16 + (size_t)row * 512 + col)       = __floats2half2_rn(f0, f1);
                *(__half2*)(C16 + (size_t)(row + 8) * 512 + col) = __floats2half2_rn(f2, f3);
            } else {
                *(float2*)(C32 + (size_t)row * 512 + col)       = make_float2(f0, f1);
                *(float2*)(C32 + (size_t)(row + 8) * 512 + col) = make_float2(f2, f3);
            }
        }
    }
}

// grid (256, 2, 3): z = matrix (0=Q,1=K,2=V), y = n-tile of 256. fp16 out.
__global__ __launch_bounds__(512, 1) void qkv_mma(const float* __restrict__ bq,
                                                  const float* __restrict__ bk,
                                                  const float* __restrict__ bv)
{
    int mat = blockIdx.z;
    const __half* Bm = g_w16 + (size_t)mat * 262144;
    const float* bias = (mat == 0) ? bq : (mat == 1) ? bk : bv;
    __half* C = (mat == 0) ? g_q16 : (mat == 1) ? g_k16 : g_v16;
    gemm_mma_body(g_x16, Bm, bias, nullptr, C, mat < 2, blockIdx.x * 128, blockIdx.y * 256);
}

// grid (256, 2). fp32 out.
__global__ __launch_bounds__(512, 1) void out_mma(float* __restrict__ out,
                                                  const float* __restrict__ bo)
{
    gemm_mma_body(g_a16, g_w16 + (size_t)3 * 262144, bo, out, nullptr, false,
                  blockIdx.x * 128, blockIdx.y * 256);
}

// ============================================================
// x -> fp16
__global__ __launch_bounds__(256) void split_x(const float* __restrict__ x)
{
    size_t i4 = ((size_t)blockIdx.x * 256 + threadIdx.x) * 4;
    float4 v = *(const float4*)(x + i4);
    *(__half2*)(g_x16 + i4)     = __floats2half2_rn(v.x, v.y);
    *(__half2*)(g_x16 + i4 + 2) = __floats2half2_rn(v.z, v.w);
}

// transpose weights: W [k][n] fp32 -> Wt [n][k] fp16. grid(16,16,4) block(32,8)
__global__ __launch_bounds__(256) void tsplit_w(const float* __restrict__ Wq,
                                                const float* __restrict__ Wk,
                                                const float* __restrict__ Wv,
                                                const float* __restrict__ Wo)
{
    const float* W = (blockIdx.z == 0) ? Wq : (blockIdx.z == 1) ? Wk
                   : (blockIdx.z == 2) ? Wv : Wo;
    __half* oh = g_w16 + (size_t)blockIdx.z * 262144;
    __shared__ float t[32][33];
    int nx = blockIdx.x * 32 + threadIdx.x;
    int k0 = blockIdx.y * 32;
#pragma unroll
    for (int j = 0; j < 4; j++)
        t[threadIdx.y + j * 8][threadIdx.x] = W[(size_t)(k0 + threadIdx.y + j * 8) * 512 + nx];
    __syncthreads();
#pragma unroll
    for (int j = 0; j < 4; j++) {
        int nr = blockIdx.x * 32 + threadIdx.y + j * 8;
        int kc = k0 + threadIdx.x;
        oh[(size_t)nr * 512 + kc] = __float2half(t[threadIdx.x][threadIdx.y + j * 8]);
    }
}

// ============================================================
// KV state via tensor cores (R9 proven) + FUSED ksum from resident K tile.
// grid (4, 64), 256 threads. Partial index layout matches kv_reduce.
__global__ __launch_bounds__(256) void kv_mma()
{
    const int bh = blockIdx.y;
    const int b = bh >> 3, h = bh & 7;
    const int tid = threadIdx.x;
    const int wid = tid >> 5, lane = tid & 31;
    const int sub = wid >> 1, nh = wid & 1;

    __shared__ __align__(1024) __half sK[128 * 64];
    __shared__ __align__(1024) __half sV[128 * 64];
    __shared__ float sks[256];
    const uint32_t kb = smem_u32(sK), vb = smem_u32(sV);

    float acc[4][4][4];
#pragma unroll
    for (int i = 0; i < 4; i++)
#pragma unroll
        for (int j = 0; j < 4; j++)
#pragma unroll
            for (int t = 0; t < 4; t++) acc[i][j][t] = 0.f;
    float ksacc = 0.f;

    const char* gk = (const char*)g_k16 + ((size_t)(b * S_ + blockIdx.x * 1024)) * 1024 + h * 128;
    const char* gv = (const char*)g_v16 + ((size_t)(b * S_ + blockIdx.x * 1024)) * 1024 + h * 128;

    const int rAl = ((lane >> 4) & 1) * 8 + (lane & 7);
    const int cA16 = (lane >> 3) & 1;
    const int rBl = ((lane >> 3) & 1) * 8 + (lane & 7);
    const int cB16 = (lane >> 4) & 1;

    // ksum lane mapping: thread covers column d over 32 rows
    const int kd  = tid & 63;           // fp16 column
    const int krg = tid >> 6;           // row group 0..3
    const int kc0 = kd >> 3;            // 16B chunk
    const int kboff = (kd & 7) * 2;     // byte within chunk

    for (int t = 0; t < 8; t++) {
#pragma unroll
        for (int i = 0; i < 4; i++) {
            int idx = i * 256 + tid;
            int r = idx >> 3, c = idx & 7;
            uint32_t so = (uint32_t)(r * 128 + ((c ^ (r & 7)) << 4));
            size_t go = (size_t)(t * 128 + r) * 1024 + c * 16;
            *(uint4*)((char*)sK + so) = *(const uint4*)(gk + go);
            *(uint4*)((char*)sV + so) = *(const uint4*)(gv + go);
        }
        __syncthreads();

        // fused ksum: sum 32 rows of column kd from resident K tile
#pragma unroll 4
        for (int rr = 0; rr < 32; rr++) {
            int r = krg * 32 + rr;
            uint32_t addr = kb + (uint32_t)(r * 128 + ((kc0 ^ (r & 7)) << 4) + kboff);
            uint16_t hbits;
            asm volatile("ld.shared.u16 %0, [%1];" : "=h"(hbits) : "r"(addr));
            ksacc += __half2float(*reinterpret_cast<__half*>(&hbits));
        }

#pragma unroll
        for (int kst = 0; kst < 2; kst++) {
            int s0 = sub * 32 + kst * 16;
            uint32_t a[4][4], bf[2][4];
#pragma unroll
            for (int mt = 0; mt < 4; mt++) {
                int r = s0 + rAl;
                int c = mt * 2 + cA16;
                ldsm4t(a[mt], kb + (uint32_t)(r * 128 + ((c ^ (r & 7)) << 4)));
            }
#pragma unroll
            for (int p = 0; p < 2; p++) {
                int r = s0 + rBl;
                int c = nh * 4 + p * 2 + cB16;
                ldsm4t(bf[p], vb + (uint32_t)(r * 128 + ((c ^ (r & 7)) << 4)));
            }
#pragma unroll
            for (int mt = 0; mt < 4; mt++)
#pragma unroll
                for (int nt = 0; nt < 4; nt++)
                    mma16816(acc[mt][nt], a[mt], &bf[nt >> 1][(nt & 1) * 2]);
        }
        __syncthreads();
    }

    float* ob = g_kvp + ((size_t)bh * 16 + blockIdx.x * 4 + sub) * 4096 + nh * 32;
    const int g = lane >> 2, t4 = lane & 3;
#pragma unroll
    for (int mt = 0; mt < 4; mt++) {
#pragma unroll
        for (int nt = 0; nt < 4; nt++) {
            int d = mt * 16 + g, col = nt * 8 + t4 * 2;
            *(float2*)(ob + (size_t)d * 64 + col)       = make_float2(acc[mt][nt][0], acc[mt][nt][1]);
            *(float2*)(ob + (size_t)(d + 8) * 64 + col) = make_float2(acc[mt][nt][2], acc[mt][nt][3]);
        }
    }

    // finish ksum partial: reduce 4 row-groups, write [bh][4][d] layout
    sks[tid] = ksacc;
    __syncthreads();
    if (tid < 64)
        g_ksp[(bh * 4 + blockIdx.x) * 64 + tid] =
            sks[tid] + sks[64 + tid] + sks[128 + tid] + sks[192 + tid];
}

// reduce partials -> KV^T fp16 hi/lo [bh][80][64]. grid 64, block 256.
__global__ __launch_bounds__(256) void kv_reduce()
{
    const int bh = blockIdx.x;
    const int tid = threadIdx.x;
    for (int idx = tid; idx < 4096; idx += 256) {
        float s = 0.f;
#pragma unroll
        for (int c = 0; c < 16; c++)
            s += g_kvp[((size_t)bh * 16 + c) * 4096 + idx];
        int d = idx >> 6, m = idx & 63;
        __half hi = __float2half(s);
        size_t o = ((size_t)bh * 80 + m) * 64 + d;
        g_kvth[o] = hi;
        g_kvtl[o] = __float2half(s - __half2float(hi));
    }
    if (tid < 64) {
        float s = g_ksp[(bh * 4 + 0) * 64 + tid] + g_ksp[(bh * 4 + 1) * 64 + tid]
                + g_ksp[(bh * 4 + 2) * 64 + tid] + g_ksp[(bh * 4 + 3) * 64 + tid];
        __half hi = __float2half(s);
        size_t o = ((size_t)bh * 80 + 64) * 64 + tid;
        g_kvth[o] = hi;
        g_kvtl[o] = __float2half(s - __half2float(hi));
    }
    for (int idx = tid; idx < 15 * 64; idx += 256) {
        size_t o = ((size_t)bh * 80 + 65) * 64 + idx;
        g_kvth[o] = __float2half(0.f);
        g_kvtl[o] = __float2half(0.f);
    }
}

// ============================================================
// Attention readout via HMMA (R10 proven): per (bh, 128-row tile),
// C[128, 80] = q_tile @ (KVT_hi + KVT_lo)^T ; col 64 = denominator.
// grid (32, 64), block 256 = 8 warps x 16 rows.
__global__ __launch_bounds__(256) void attn_mma()
{
    const int bh = blockIdx.y;
    const int b = bh >> 3, h = bh & 7;
    const int l0 = blockIdx.x * 128;
    const int tid = threadIdx.x;
    const int wid = tid >> 5, lane = tid & 31;

    __shared__ __align__(1024) __half sQ[128 * 64];
    __shared__ __align__(1024) __half sB[2][80 * 64];
    __shared__ float sDen[128];

#pragma unroll
    for (int i = 0; i < 4; i++) {
        int idx = i * 256 + tid;
        int r = idx >> 3, c = idx & 7;
        uint32_t so = (uint32_t)(r * 128 + ((c ^ (r & 7)) << 4));
        size_t go = (((size_t)(b * S_ + l0 + r)) * 512 + h * 64) * 2 + c * 16;
        *(uint4*)((char*)sQ + so) = *(const uint4*)((const char*)g_q16 + go);
    }
#pragma unroll
    for (int i = 0; i < 5; i++) {
        int idx = i * 256 + tid;
        int r = idx >> 3, c = idx & 7;   // r in 0..159
        int arr = r >= 80;
        int rr = arr ? r - 80 : r;
        uint32_t so = (uint32_t)(rr * 128 + ((c ^ (rr & 7)) << 4));
        size_t go = (((size_t)bh * 80 + rr) * 64) * 2 + c * 16;
        const char* src = arr ? (const char*)g_kvtl : (const char*)g_kvth;
        *(uint4*)((char*)sB[arr] + so) = *(const uint4*)(src + go);
    }
    __syncthreads();

    const uint32_t qb = smem_u32(sQ);
    const uint32_t bb0 = smem_u32(sB[0]);
    const uint32_t bb1 = smem_u32(sB[1]);

    const int rA  = wid * 16 + (lane & 15);
    const int khA = (lane >> 4) & 1;
    const int swA = rA & 7;
    const int rBl = (lane & 7) + ((lane >> 1) & 8);
    const int khB = (lane >> 3) & 1;

    float acc[10][4];
#pragma unroll
    for (int n = 0; n < 10; n++)
#pragma unroll
        for (int t = 0; t < 4; t++) acc[n][t] = 0.f;

#pragma unroll
    for (int ks = 0; ks < 4; ks++) {
        uint32_t a[4];
        int cA = ks * 2 + khA;
        ldsm4(a, qb + (uint32_t)(rA * 128 + ((cA ^ swA) << 4)));
#pragma unroll
        for (int arr = 0; arr < 2; arr++) {
            uint32_t base = arr ? bb1 : bb0;
#pragma unroll
            for (int p = 0; p < 5; p++) {
                uint32_t bf[4];
                int rB = p * 16 + rBl;
                int cB = ks * 2 + khB;
                ldsm4(bf, base + (uint32_t)(rB * 128 + ((cB ^ (rB & 7)) << 4)));
                mma16816(acc[p * 2], a, bf + 0);
                if (p < 4) mma16816(acc[p * 2 + 1], a, bf + 2);
            }
        }
    }

    const int g = lane >> 2, t4 = lane & 3;
    if (t4 == 0) {
        sDen[wid * 16 + g]     = acc[8][0];
        sDen[wid * 16 + g + 8] = acc[8][2];
    }
    __syncthreads();

    int row0 = wid * 16 + g;
    float z0 = 1.0f / (sDen[row0] + EPS_);
    float z1 = 1.0f / (sDen[row0 + 8] + EPS_);
    __half* o0 = g_a16 + ((size_t)(b * S_ + l0 + row0)) * 512 + h * 64;
    __half* o1 = o0 + (size_t)8 * 512;
#pragma unroll
    for (int nt = 0; nt < 8; nt++) {
        int col = nt * 8 + t4 * 2;
        *(__half2*)(o0 + col) = __floats2half2_rn(acc[nt][0] * z0, acc[nt][1] * z0);
        *(__half2*)(o1 + col) = __floats2half2_rn(acc[nt][2] * z1, acc[nt][3] * z1);
    }
}

// ============================================================
extern "C" void kernel_launch(void* const* d_in, const int* in_sizes, int n_in,
                              void* d_out, int out_size)
{
    const float* x  = (const float*)d_in[0];
    const float* Wq = (const float*)d_in[1];
    const float* bq = (const float*)d_in[2];
    const float* Wk = (const float*)d_in[3];
    const float* bk = (const float*)d_in[4];
    const float* Wv = (const float*)d_in[5];
    const float* bv = (const float*)d_in[6];
    const float* Wo = (const float*)d_in[7];
    const float* bo = (const float*)d_in[8];
    float* out = (float*)d_out;

    cudaFuncSetAttribute(qkv_mma, cudaFuncAttributeMaxDynamicSharedMemorySize, GEMM_DSMEM);
    cudaFuncSetAttribute(out_mma, cudaFuncAttributeMaxDynamicSharedMemorySize, GEMM_DSMEM);

    split_x<<<(M_ * E_) / (256 * 4), 256>>>(x);
    tsplit_w<<<dim3(16, 16, 4), dim3(32, 8)>>>(Wq, Wk, Wv, Wo);
    qkv_mma<<<dim3(M_ / 128, 2, 3), 512, GEMM_DSMEM>>>(bq, bk, bv);
    kv_mma<<<dim3(4, 64), 256>>>();
    kv_reduce<<<64, 256>>>();
    attn_mma<<<dim3(32, 64), 256>>>();
    out_mma<<<dim3(M_ / 128, 2), 512, GEMM_DSMEM>>>(out, bo);
}

// round 16
// speedup vs baseline: 1.7683x; 1.0062x over previous
#include <cuda_runtime.h>
#include <cuda_fp16.h>
#include <math.h>
#include <stdint.h>

#define B_   8
#define S_   4096
#define E_   512
#define H_   8
#define D_   64
#define M_   (B_ * S_)      // 32768 rows
#define EPS_ 1e-6f

// -------- scratch (device globals; no allocations allowed) --------
__device__ __align__(16) float g_kvp[(size_t)B_ * H_ * 16 * D_ * D_];  // [bh][16][d][m]
__device__ __align__(16) float g_ksp[B_ * H_ * 4 * D_];                // [bh][4][d]
// KV^T per head, fp16 hi/lo, [bh][80][64]; row 64 = ksum, rows 65-79 zero.
__device__ __align__(16) __half g_kvth[64 * 80 * 64];
__device__ __align__(16) __half g_kvtl[64 * 80 * 64];
// fp16 operands
__device__ __align__(16) __half g_x16[(size_t)M_ * E_];
__device__ __align__(16) __half g_q16[(size_t)M_ * E_];
__device__ __align__(16) __half g_k16[(size_t)M_ * E_];
__device__ __align__(16) __half g_v16[(size_t)M_ * E_];
__device__ __align__(16) __half g_a16[(size_t)M_ * E_];
__device__ __align__(16) __half g_w16[4 * 512 * 512];   // transposed [n][k]

// ================= portable PTX helpers =================
static __device__ __forceinline__ uint32_t smem_u32(const void* p) {
    uint32_t a;
    asm("{ .reg .u64 t; cvta.to.shared.u64 t, %1; cvt.u32.u64 %0, t; }" : "=r"(a) : "l"(p));
    return a;
}
static __device__ __forceinline__ void ldsm4(uint32_t* r, uint32_t addr) {
    asm volatile("ldmatrix.sync.aligned.m8n8.x4.shared.b16 {%0,%1,%2,%3}, [%4];"
                 : "=r"(r[0]), "=r"(r[1]), "=r"(r[2]), "=r"(r[3]) : "r"(addr));
}
static __device__ __forceinline__ void ldsm4t(uint32_t* r, uint32_t addr) {
    asm volatile("ldmatrix.sync.aligned.m8n8.x4.trans.shared.b16 {%0,%1,%2,%3}, [%4];"
                 : "=r"(r[0]), "=r"(r[1]), "=r"(r[2]), "=r"(r[3]) : "r"(addr));
}
static __device__ __forceinline__ void mma16816(float* c, const uint32_t* a, const uint32_t* b) {
    asm volatile("mma.sync.aligned.m16n8k16.row.col.f32.f16.f16.f32 "
                 "{%0,%1,%2,%3}, {%4,%5,%6,%7}, {%8,%9}, {%0,%1,%2,%3};"
                 : "+f"(c[0]), "+f"(c[1]), "+f"(c[2]), "+f"(c[3])
                 : "r"(a[0]), "r"(a[1]), "r"(a[2]), "r"(a[3]), "r"(b[0]), "r"(b[1]));
}
static __device__ __forceinline__ void cp16(uint32_t dst, const void* src) {
    asm volatile("cp.async.cg.shared.global [%0], [%1], 16;" :: "r"(dst), "l"(src));
}
static __device__ __forceinline__ void cp_commit() {
    asm volatile("cp.async.commit_group;");
}
template <int N> static __device__ __forceinline__ void cp_wait() {
    asm volatile("cp.async.wait_group %0;" :: "n"(N));
}

// ============================================================
// HMMA fp16 GEMM (R13 proven), BM=128 BN=256 BK=64, 512 threads (16 warps,
// 4m x 4n), warp tile 32x64, 2-stage cp.async pipeline.
// Dynamic SMEM 96KB: 2 stages x (A 16K | B 32K), XOR-swizzled 16B chunks.
// ============================================================
#define GSTAGE 49152
#define GEMM_DSMEM (2 * GSTAGE)

static __device__ __forceinline__ void gemm_issue(
    uint32_t sb, int tid, int k0, int m0, int n0,
    const char* Ab, const char* Bb)
{
#pragma unroll
    for (int i = 0; i < 2; i++) {
        int idx = i * 512 + tid;
        int r = idx >> 3, c = idx & 7;
        uint32_t so = (uint32_t)(r * 128 + ((c ^ (r & 7)) << 4));
        size_t go = ((size_t)(m0 + r) * 512 + k0) * 2 + c * 16;
        cp16(sb + so, Ab + go);
    }
#pragma unroll
    for (int i = 0; i < 4; i++) {
        int idx = i * 512 + tid;
        int r = idx >> 3, c = idx & 7;
        uint32_t so = (uint32_t)(16384 + r * 128 + ((c ^ (r & 7)) << 4));
        size_t go = ((size_t)(n0 + r) * 512 + k0) * 2 + c * 16;
        cp16(sb + so, Bb + go);
    }
    cp_commit();
}

static __device__ __forceinline__ void gemm_mma_body(
    const __half* __restrict__ A, const __half* __restrict__ Bm,
    const float* __restrict__ bias, float* __restrict__ C32,
    __half* __restrict__ C16, bool act, int m0, int n0)
{
    extern __shared__ __align__(1024) uint8_t dsm[];
    const int tid = threadIdx.x;
    const int wid = tid >> 5, lane = tid & 31;
    const int wm = wid & 3;          // 0..3 -> 32-row m group
    const int wn = wid >> 2;         // 0..3 -> 64-col n group
    const uint32_t sbase = smem_u32(dsm);

    float acc[2][8][4];
#pragma unroll
    for (int i = 0; i < 2; i++)
#pragma unroll
        for (int j = 0; j < 8; j++)
#pragma unroll
            for (int t = 0; t < 4; t++) acc[i][j][t] = 0.f;

    const int rA  = wm * 32 + (lane & 15);
    const int khA = (lane >> 4) & 1;
    const int swA = rA & 7;
    const int rBl = wn * 64 + (lane & 7) + ((lane >> 1) & 8);
    const int khB = (lane >> 3) & 1;

    const char* Ab = (const char*)A;
    const char* Bb = (const char*)Bm;

    gemm_issue(sbase, tid, 0, m0, n0, Ab, Bb);

    for (int kb = 0; kb < 8; kb++) {
        if (kb < 7) {
            gemm_issue(sbase + ((kb + 1) & 1) * GSTAGE, tid, (kb + 1) * 64, m0, n0, Ab, Bb);
            cp_wait<1>();
        } else {
            cp_wait<0>();
        }
        __syncthreads();

        const uint32_t st = sbase + (kb & 1) * GSTAGE;
        const uint32_t sA = st, sB = st + 16384;

#pragma unroll
        for (int ks = 0; ks < 4; ks++) {
            uint32_t a[8], bf[16];
            int cA = ks * 2 + khA;
            uint32_t aoff = (uint32_t)(rA * 128 + ((cA ^ swA) << 4));
            ldsm4(a + 0, sA + aoff);
            ldsm4(a + 4, sA + aoff + 2048);
#pragma unroll
            for (int p = 0; p < 4; p++) {
                int rB = rBl + p * 16;
                int cB = ks * 2 + khB;
                ldsm4(bf + 4 * p, sB + (uint32_t)(rB * 128 + ((cB ^ (rB & 7)) << 4)));
            }
#pragma unroll
            for (int mt = 0; mt < 2; mt++)
#pragma unroll
                for (int nt = 0; nt < 8; nt++)
                    mma16816(acc[mt][nt], a + 4 * mt, bf + nt * 2);
        }
        __syncthreads();
    }

    const int g = lane >> 2, t4 = lane & 3;
#pragma unroll
    for (int mt = 0; mt < 2; mt++) {
#pragma unroll
        for (int nt = 0; nt < 8; nt++) {
            int row = m0 + wm * 32 + mt * 16 + g;
            int col = n0 + wn * 64 + nt * 8 + t4 * 2;
            float b0 = bias[col], b1 = bias[col + 1];
            float f0 = acc[mt][nt][0] + b0;
            float f1 = acc[mt][nt][1] + b1;
            float f2 = acc[mt][nt][2] + b0;
            float f3 = acc[mt][nt][3] + b1;
            if (act) {
                f0 = (f0 > 0.f) ? (f0 + 1.f) : __expf(f0);
                f1 = (f1 > 0.f) ? (f1 + 1.f) : __expf(f1);
                f2 = (f2 > 0.f) ? (f2 + 1.f) : __expf(f2);
                f3 = (f3 > 0.f) ? (f3 + 1.f) : __expf(f3);
            }
            if (C16) {
                *(__half2*)(C16 + (size_t)row * 512 + col)       = __floats2half2_rn(f0, f1);
                *(__half2*)(C16 + (size_t)(row + 8) * 512 + col) = __floats2half2_rn(f2, f3);
            } else {
                *(float2*)(C32 + (size_t)row * 512 + col)       = make_float2(f0, f1);
                *(float2*)(C32 + (size_t)(row + 8) * 512 + col) = make_float2(f2, f3);
            }
        }
    }
}

// grid (256, 2, 3): z = matrix (0=Q,1=K,2=V), y = n-tile of 256. fp16 out.
__global__ __launch_bounds__(512, 1) void qkv_mma(const float* __restrict__ bq,
                                                  const float* __restrict__ bk,
                                                  const float* __restrict__ bv)
{
    int mat = blockIdx.z;
    const __half* Bm = g_w16 + (size_t)mat * 262144;
    const float* bias = (mat == 0) ? bq : (mat == 1) ? bk : bv;
    __half* C = (mat == 0) ? g_q16 : (mat == 1) ? g_k16 : g_v16;
    gemm_mma_body(g_x16, Bm, bias, nullptr, C, mat < 2, blockIdx.x * 128, blockIdx.y * 256);
}

// grid (256, 2). fp32 out.
__global__ __launch_bounds__(512, 1) void out_mma(float* __restrict__ out,
                                                  const float* __restrict__ bo)
{
    gemm_mma_body(g_a16, g_w16 + (size_t)3 * 262144, bo, out, nullptr, false,
                  blockIdx.x * 128, blockIdx.y * 256);
}

// ============================================================
// prep: fused split_x + weight transpose/convert. grid 17408, block 256.
// blocks [0, 16384): x -> fp16. blocks [16384, 17408): W -> Wt fp16.
__global__ __launch_bounds__(256) void prep(const float* __restrict__ x,
                                            const float* __restrict__ Wq,
                                            const float* __restrict__ Wk,
                                            const float* __restrict__ Wv,
                                            const float* __restrict__ Wo)
{
    if (blockIdx.x < 16384) {
        size_t i4 = ((size_t)blockIdx.x * 256 + threadIdx.x) * 4;
        float4 v = *(const float4*)(x + i4);
        *(__half2*)(g_x16 + i4)     = __floats2half2_rn(v.x, v.y);
        *(__half2*)(g_x16 + i4 + 2) = __floats2half2_rn(v.z, v.w);
        return;
    }
    int bid = blockIdx.x - 16384;          // 0..1023
    int z = bid >> 8;                      // matrix 0..3
    int bx = bid & 15;                     // n-block
    int by = (bid >> 4) & 15;              // k-block
    const float* W = (z == 0) ? Wq : (z == 1) ? Wk : (z == 2) ? Wv : Wo;
    __half* oh = g_w16 + (size_t)z * 262144;
    __shared__ float t[32][33];
    int tx = threadIdx.x & 31, ty = threadIdx.x >> 5;   // 32 x 8
    int nx = bx * 32 + tx;
    int k0 = by * 32;
#pragma unroll
    for (int j = 0; j < 4; j++)
        t[ty + j * 8][tx] = W[(size_t)(k0 + ty + j * 8) * 512 + nx];
    __syncthreads();
#pragma unroll
    for (int j = 0; j < 4; j++) {
        int nr = bx * 32 + ty + j * 8;
        int kc = k0 + tx;
        oh[(size_t)nr * 512 + kc] = __float2half(t[tx][ty + j * 8]);
    }
}

// ============================================================
// KV state via tensor cores (R9 proven) + MMA-based fused ksum:
// ksum partial computed as K^T @ ones8 using the already-loaded A fragments.
// grid (4, 64), 256 threads. Partial layouts unchanged.
__global__ __launch_bounds__(256) void kv_mma()
{
    const int bh = blockIdx.y;
    const int b = bh >> 3, h = bh & 7;
    const int tid = threadIdx.x;
    const int wid = tid >> 5, lane = tid & 31;
    const int sub = wid >> 1, nh = wid & 1;

    __shared__ __align__(1024) __half sK[128 * 64];
    __shared__ __align__(1024) __half sV[128 * 64];
    __shared__ __align__(32) __half sOne[16 * 16];   // 16 rows x 16 cols; col0 = 1
    __shared__ float sks[256];
    const uint32_t kb = smem_u32(sK), vb = smem_u32(sV);
    const uint32_t oneb = smem_u32(sOne);

    // init ones tile (col 0 of each 16-col row = 1.0)
    if (tid < 256) { /* all threads */ }
    {
        int row = tid >> 4, col = tid & 15;
        if (tid < 256) sOne[row * 16 + col] = __float2half((col == 0) ? 1.f : 0.f);
    }

    float acc[4][4][4];
#pragma unroll
    for (int i = 0; i < 4; i++)
#pragma unroll
        for (int j = 0; j < 4; j++)
#pragma unroll
            for (int t = 0; t < 4; t++) acc[i][j][t] = 0.f;
    float accK[4][4];
#pragma unroll
    for (int i = 0; i < 4; i++)
#pragma unroll
        for (int t = 0; t < 4; t++) accK[i][t] = 0.f;

    const char* gk = (const char*)g_k16 + ((size_t)(b * S_ + blockIdx.x * 1024)) * 1024 + h * 128;
    const char* gv = (const char*)g_v16 + ((size_t)(b * S_ + blockIdx.x * 1024)) * 1024 + h * 128;

    const int rAl = ((lane >> 4) & 1) * 8 + (lane & 7);
    const int cA16 = (lane >> 3) & 1;
    const int rBl = ((lane >> 3) & 1) * 8 + (lane & 7);
    const int cB16 = (lane >> 4) & 1;

    __syncthreads();
    // constant ones B-fragment (same lane pattern as V, row stride 32B, no swizzle)
    uint32_t bfOne[4];
    ldsm4t(bfOne, oneb + (uint32_t)(rBl * 32 + cB16 * 16));

    for (int t = 0; t < 8; t++) {
#pragma unroll
        for (int i = 0; i < 4; i++) {
            int idx = i * 256 + tid;
            int r = idx >> 3, c = idx & 7;
            uint32_t so = (uint32_t)(r * 128 + ((c ^ (r & 7)) << 4));
            size_t go = (size_t)(t * 128 + r) * 1024 + c * 16;
            *(uint4*)((char*)sK + so) = *(const uint4*)(gk + go);
            *(uint4*)((char*)sV + so) = *(const uint4*)(gv + go);
        }
        __syncthreads();

#pragma unroll
        for (int kst = 0; kst < 2; kst++) {
            int s0 = sub * 32 + kst * 16;
            uint32_t a[4][4], bf[2][4];
#pragma unroll
            for (int mt = 0; mt < 4; mt++) {
                int r = s0 + rAl;
                int c = mt * 2 + cA16;
                ldsm4t(a[mt], kb + (uint32_t)(r * 128 + ((c ^ (r & 7)) << 4)));
            }
#pragma unroll
            for (int p = 0; p < 2; p++) {
                int r = s0 + rBl;
                int c = nh * 4 + p * 2 + cB16;
                ldsm4t(bf[p], vb + (uint32_t)(r * 128 + ((c ^ (r & 7)) << 4)));
            }
#pragma unroll
            for (int mt = 0; mt < 4; mt++)
#pragma unroll
                for (int nt = 0; nt < 4; nt++)
                    mma16816(acc[mt][nt], a[mt], &bf[nt >> 1][(nt & 1) * 2]);
            if (nh == 0) {
#pragma unroll
                for (int mt = 0; mt < 4; mt++)
                    mma16816(accK[mt], a[mt], bfOne);
            }
        }
        __syncthreads();
    }

    float* ob = g_kvp + ((size_t)bh * 16 + blockIdx.x * 4 + sub) * 4096 + nh * 32;
    const int g = lane >> 2, t4 = lane & 3;
#pragma unroll
    for (int mt = 0; mt < 4; mt++) {
#pragma unroll
        for (int nt = 0; nt < 4; nt++) {
            int d = mt * 16 + g, col = nt * 8 + t4 * 2;
            *(float2*)(ob + (size_t)d * 64 + col)       = make_float2(acc[mt][nt][0], acc[mt][nt][1]);
            *(float2*)(ob + (size_t)(d + 8) * 64 + col) = make_float2(acc[mt][nt][2], acc[mt][nt][3]);
        }
    }

    // ksum: col 0 of accK holds sum over this sub's rows; reduce across subs.
    if (nh == 0 && t4 == 0) {
#pragma unroll
        for (int mt = 0; mt < 4; mt++) {
            sks[sub * 64 + mt * 16 + g]     = accK[mt][0];
            sks[sub * 64 + mt * 16 + g + 8] = accK[mt][2];
        }
    }
    __syncthreads();
    if (tid < 64)
        g_ksp[(bh * 4 + blockIdx.x) * 64 + tid] =
            sks[tid] + sks[64 + tid] + sks[128 + tid] + sks[192 + tid];
}

// reduce partials -> KV^T fp16 hi/lo [bh][80][64]. grid 64, block 256.
__global__ __launch_bounds__(256) void kv_reduce()
{
    const int bh = blockIdx.x;
    const int tid = threadIdx.x;
    for (int idx = tid; idx < 4096; idx += 256) {
        float s = 0.f;
#pragma unroll
        for (int c = 0; c < 16; c++)
            s += g_kvp[((size_t)bh * 16 + c) * 4096 + idx];
        int d = idx >> 6, m = idx & 63;
        __half hi = __float2half(s);
        size_t o = ((size_t)bh * 80 + m) * 64 + d;
        g_kvth[o] = hi;
        g_kvtl[o] = __float2half(s - __half2float(hi));
    }
    if (tid < 64) {
        float s = g_ksp[(bh * 4 + 0) * 64 + tid] + g_ksp[(bh * 4 + 1) * 64 + tid]
                + g_ksp[(bh * 4 + 2) * 64 + tid] + g_ksp[(bh * 4 + 3) * 64 + tid];
        __half hi = __float2half(s);
        size_t o = ((size_t)bh * 80 + 64) * 64 + tid;
        g_kvth[o] = hi;
        g_kvtl[o] = __float2half(s - __half2float(hi));
    }
    for (int idx = tid; idx < 15 * 64; idx += 256) {
        size_t o = ((size_t)bh * 80 + 65) * 64 + idx;
        g_kvth[o] = __float2half(0.f);
        g_kvtl[o] = __float2half(0.f);
    }
}

// ============================================================
// Attention readout via HMMA (R10 proven): per (bh, 128-row tile),
// C[128, 80] = q_tile @ (KVT_hi + KVT_lo)^T ; col 64 = denominator.
// grid (32, 64), block 256 = 8 warps x 16 rows.
__global__ __launch_bounds__(256) void attn_mma()
{
    const int bh = blockIdx.y;
    const int b = bh >> 3, h = bh & 7;
    const int l0 = blockIdx.x * 128;
    const int tid = threadIdx.x;
    const int wid = tid >> 5, lane = tid & 31;

    __shared__ __align__(1024) __half sQ[128 * 64];
    __shared__ __align__(1024) __half sB[2][80 * 64];
    __shared__ float sDen[128];

#pragma unroll
    for (int i = 0; i < 4; i++) {
        int idx = i * 256 + tid;
        int r = idx >> 3, c = idx & 7;
        uint32_t so = (uint32_t)(r * 128 + ((c ^ (r & 7)) << 4));
        size_t go = (((size_t)(b * S_ + l0 + r)) * 512 + h * 64) * 2 + c * 16;
        *(uint4*)((char*)sQ + so) = *(const uint4*)((const char*)g_q16 + go);
    }
#pragma unroll
    for (int i = 0; i < 5; i++) {
        int idx = i * 256 + tid;
        int r = idx >> 3, c = idx & 7;   // r in 0..159
        int arr = r >= 80;
        int rr = arr ? r - 80 : r;
        uint32_t so = (uint32_t)(rr * 128 + ((c ^ (rr & 7)) << 4));
        size_t go = (((size_t)bh * 80 + rr) * 64) * 2 + c * 16;
        const char* src = arr ? (const char*)g_kvtl : (const char*)g_kvth;
        *(uint4*)((char*)sB[arr] + so) = *(const uint4*)(src + go);
    }
    __syncthreads();

    const uint32_t qb = smem_u32(sQ);
    const uint32_t bb0 = smem_u32(sB[0]);
    const uint32_t bb1 = smem_u32(sB[1]);

    const int rA  = wid * 16 + (lane & 15);
    const int khA = (lane >> 4) & 1;
    const int swA = rA & 7;
    const int rBl = (lane & 7) + ((lane >> 1) & 8);
    const int khB = (lane >> 3) & 1;

    float acc[10][4];
#pragma unroll
    for (int n = 0; n < 10; n++)
#pragma unroll
        for (int t = 0; t < 4; t++) acc[n][t] = 0.f;

#pragma unroll
    for (int ks = 0; ks < 4; ks++) {
        uint32_t a[4];
        int cA = ks * 2 + khA;
        ldsm4(a, qb + (uint32_t)(rA * 128 + ((cA ^ swA) << 4)));
#pragma unroll
        for (int arr = 0; arr < 2; arr++) {
            uint32_t base = arr ? bb1 : bb0;
#pragma unroll
            for (int p = 0; p < 5; p++) {
                uint32_t bf[4];
                int rB = p * 16 + rBl;
                int cB = ks * 2 + khB;
                ldsm4(bf, base + (uint32_t)(rB * 128 + ((cB ^ (rB & 7)) << 4)));
                mma16816(acc[p * 2], a, bf + 0);
                if (p < 4) mma16816(acc[p * 2 + 1], a, bf + 2);
            }
        }
    }

    const int g = lane >> 2, t4 = lane & 3;
    if (t4 == 0) {
        sDen[wid * 16 + g]     = acc[8][0];
        sDen[wid * 16 + g + 8] = acc[8][2];
    }
    __syncthreads();

    int row0 = wid * 16 + g;
    float z0 = 1.0f / (sDen[row0] + EPS_);
    float z1 = 1.0f / (sDen[row0 + 8] + EPS_);
    __half* o0 = g_a16 + ((size_t)(b * S_ + l0 + row0)) * 512 + h * 64;
    __half* o1 = o0 + (size_t)8 * 512;
#pragma unroll
    for (int nt = 0; nt < 8; nt++) {
        int col = nt * 8 + t4 * 2;
        *(__half2*)(o0 + col) = __floats2half2_rn(acc[nt][0] * z0, acc[nt][1] * z0);
        *(__half2*)(o1 + col) = __floats2half2_rn(acc[nt][2] * z1, acc[nt][3] * z1);
    }
}

// ============================================================
extern "C" void kernel_launch(void* const* d_in, const int* in_sizes, int n_in,
                              void* d_out, int out_size)
{
    const float* x  = (const float*)d_in[0];
    const float* Wq = (const float*)d_in[1];
    const float* bq = (const float*)d_in[2];
    const float* Wk = (const float*)d_in[3];
    const float* bk = (const float*)d_in[4];
    const float* Wv = (const float*)d_in[5];
    const float* bv = (const float*)d_in[6];
    const float* Wo = (const float*)d_in[7];
    const float* bo = (const float*)d_in[8];
    float* out = (float*)d_out;

    cudaFuncSetAttribute(qkv_mma, cudaFuncAttributeMaxDynamicSharedMemorySize, GEMM_DSMEM);
    cudaFuncSetAttribute(out_mma, cudaFuncAttributeMaxDynamicSharedMemorySize, GEMM_DSMEM);

    prep<<<17408, 256>>>(x, Wq, Wk, Wv, Wo);
    qkv_mma<<<dim3(M_ / 128, 2, 3), 512, GEMM_DSMEM>>>(bq, bk, bv);
    kv_mma<<<dim3(4, 64), 256>>>();
    kv_reduce<<<64, 256>>>();
    attn_mma<<<dim3(32, 64), 256>>>();
    out_mma<<<dim3(M_ / 128, 2), 512, GEMM_DSMEM>>>(out, bo);
}